// round 1
// baseline (speedup 1.0000x reference)
#include <cuda_runtime.h>
#include <cstdint>

// Problem constants (shapes are fixed by the dataset)
#define D_IN 64
#define D_OUT 64
#define NCLUS 8
#define NHEAD 4
#define NC 32            // NHEAD*NCLUS
#define EMAX 400000
#define NMAX 50000

typedef unsigned long long ull;

// ---------------- scratch (device globals; no allocation allowed) -------------
__device__ float g_w[EMAX * 8];        // per-edge softmax weights
__device__ int   g_deg[NMAX];
__device__ int   g_off[NMAX + 1];
__device__ int   g_cur[NMAX];
__device__ int   g_sorted[EMAX];

// ---------------- packed f32x2 helpers ---------------------------------------
__device__ __forceinline__ ull fma2(ull a, ull b, ull c) {
    ull d;
    asm("fma.rn.f32x2 %0, %1, %2, %3;" : "=l"(d) : "l"(a), "l"(b), "l"(c));
    return d;
}
__device__ __forceinline__ ull packf2(float lo, float hi) {
    ull r;
    asm("mov.b64 %0, {%1, %2};" : "=l"(r)
        : "r"(__float_as_uint(lo)), "r"(__float_as_uint(hi)));
    return r;
}
__device__ __forceinline__ void unpackf2(ull v, float& lo, float& hi) {
    unsigned a, b;
    asm("mov.b64 {%0, %1}, %2;" : "=r"(a), "=r"(b) : "l"(v));
    lo = __uint_as_float(a); hi = __uint_as_float(b);
}

// ============================================================================
// K1: per-edge cluster weights w[E,8] + degree histogram
//   x = x_j + e_ij ; dist_c = ||k_c||^2 + ||x||^2 - 2 k_c.x ; t = 1/(1+dist)
//   per-head normalize *10, mean over heads, softmax over 8 clusters
// smem: ksm[64][32] (d-major, f32x2-pair friendly), sx[64][257], knorm[32]
// ============================================================================
#define SXS 257
#define K1_SMEM ((2048 + 64 * SXS + 32) * 4)

__global__ __launch_bounds__(256) void k_weights(
    const float* __restrict__ xj, const float* __restrict__ eij,
    const int* __restrict__ index, const float* __restrict__ kc, int E)
{
    extern __shared__ float sm[];
    float* ksm   = sm;                    // 2048 floats
    float* sx    = sm + 2048;             // 64*257 floats
    float* knorm = sm + 2048 + 64 * SXS;  // 32 floats
    const int tid = threadIdx.x;

    // k transposed: ksm[d*32 + c] = k[c*64 + d]
    for (int i = tid; i < 2048; i += 256) {
        int c = i >> 6, d = i & 63;
        ksm[d * 32 + c] = kc[i];
    }
    __syncthreads();
    if (tid < 32) {
        float s = 0.f;
        for (int d = 0; d < 64; ++d) { float v = ksm[d * 32 + tid]; s = fmaf(v, v, s); }
        knorm[tid] = s;
    }

    // stage x = x_j + e_ij transposed into sx[d][e]
    const int e0 = blockIdx.x * 256;
    const float4* xj4 = (const float4*)xj;
    const float4* ei4 = (const float4*)eij;
    const long base4 = (long)e0 * 16;
#pragma unroll
    for (int i = 0; i < 16; ++i) {
        int f = i * 256 + tid;
        int e = f >> 4, dq = f & 15;
        float4 a = make_float4(0.f, 0.f, 0.f, 0.f);
        if (e0 + e < E) {
            float4 xa = xj4[base4 + f];
            float4 xb = ei4[base4 + f];
            a.x = xa.x + xb.x; a.y = xa.y + xb.y; a.z = xa.z + xb.z; a.w = xa.w + xb.w;
        }
        sx[(dq * 4 + 0) * SXS + e] = a.x;
        sx[(dq * 4 + 1) * SXS + e] = a.y;
        sx[(dq * 4 + 2) * SXS + e] = a.z;
        sx[(dq * 4 + 3) * SXS + e] = a.w;
    }
    __syncthreads();

    const int e = e0 + tid;
    if (e >= E) return;

    ull acc[16];
#pragma unroll
    for (int i = 0; i < 16; ++i) acc[i] = 0ull;
    float xn = 0.f;

#pragma unroll 4
    for (int d = 0; d < 64; ++d) {
        float xv = sx[d * SXS + tid];
        xn = fmaf(xv, xv, xn);
        ull xv2 = packf2(xv, xv);
        const longlong2* kr = (const longlong2*)(ksm + d * 32);
#pragma unroll
        for (int p = 0; p < 8; ++p) {
            longlong2 kk = kr[p];
            acc[2 * p]     = fma2(xv2, (ull)kk.x, acc[2 * p]);
            acc[2 * p + 1] = fma2(xv2, (ull)kk.y, acc[2 * p + 1]);
        }
    }

    float t[32];
#pragma unroll
    for (int p = 0; p < 16; ++p) {
        float lo, hi;
        unpackf2(acc[p], lo, hi);
        int c = 2 * p;
        float dist = fmaxf(knorm[c] + xn - 2.f * lo, 0.f);
        t[c] = __frcp_rn(1.f + dist);
        c = 2 * p + 1;
        dist = fmaxf(knorm[c] + xn - 2.f * hi, 0.f);
        t[c] = __frcp_rn(1.f + dist);
    }

    float m[8];
#pragma unroll
    for (int kk = 0; kk < 8; ++kk) m[kk] = 0.f;
#pragma unroll
    for (int h = 0; h < 4; ++h) {
        float hs = 0.f;
#pragma unroll
        for (int kk = 0; kk < 8; ++kk) hs += t[h * 8 + kk];
        float inv = __frcp_rn(hs);
#pragma unroll
        for (int kk = 0; kk < 8; ++kk) m[kk] = fmaf(t[h * 8 + kk], inv, m[kk]);
    }
    // * TAU / HEADS = 10/4
    float mx = -1e30f;
#pragma unroll
    for (int kk = 0; kk < 8; ++kk) { m[kk] *= 2.5f; mx = fmaxf(mx, m[kk]); }
    float se = 0.f;
    float ex[8];
#pragma unroll
    for (int kk = 0; kk < 8; ++kk) { ex[kk] = __expf(m[kk] - mx); se += ex[kk]; }
    float inv = __frcp_rn(se);

    float4* wout = (float4*)g_w;
    wout[e * 2]     = make_float4(ex[0] * inv, ex[1] * inv, ex[2] * inv, ex[3] * inv);
    wout[e * 2 + 1] = make_float4(ex[4] * inv, ex[5] * inv, ex[6] * inv, ex[7] * inv);

    atomicAdd(&g_deg[index[e]], 1);
}

// ============================================================================
// K2: single-block exclusive scan of g_deg -> g_off, g_cur
// ============================================================================
__global__ void k_scan(int N)
{
    __shared__ int wsum[32];
    __shared__ int carry;
    const int tid = threadIdx.x;
    const int lane = tid & 31, wid = tid >> 5;
    if (tid == 0) carry = 0;
    __syncthreads();
    const int iters = N / 1024 + 1;
    for (int it = 0; it < iters; ++it) {
        int idx = it * 1024 + tid;
        int v = (idx < N) ? g_deg[idx] : 0;
        int x = v;
#pragma unroll
        for (int o = 1; o < 32; o <<= 1) {
            int y = __shfl_up_sync(0xffffffffu, x, o);
            if (lane >= o) x += y;
        }
        if (lane == 31) wsum[wid] = x;
        __syncthreads();
        if (wid == 0) {
            int s = wsum[lane];
            int xs = s;
#pragma unroll
            for (int o = 1; o < 32; o <<= 1) {
                int y = __shfl_up_sync(0xffffffffu, xs, o);
                if (lane >= o) xs += y;
            }
            wsum[lane] = xs - s;  // exclusive warp prefix
        }
        __syncthreads();
        int base = carry;
        int excl = x - v + wsum[wid];
        if (idx < N) { g_off[idx] = base + excl; g_cur[idx] = base + excl; }
        else if (idx == N) { g_off[N] = base + excl; }
        __syncthreads();
        if (tid == 1023) carry = base + x + wsum[31];
        __syncthreads();
    }
}

// ============================================================================
// K3: scatter edge ids into CSR order
// ============================================================================
__global__ void k_scatter(const int* __restrict__ index, int E)
{
    int e = blockIdx.x * 256 + threadIdx.x;
    if (e < E) {
        int pos = atomicAdd(&g_cur[index[e]], 1);
        g_sorted[pos] = e;
    }
}

// ============================================================================
// K4: per-node gather of w (x) msg into smem + fused GEMM with W, bias, leaky
// persistent blocks; W (128KB) loaded to smem once per block
// smem: Wsm[512*64] + a[32][520] + b[64]  = 197888 B  -> 1 block / SM
// ============================================================================
#define ASTR 520
#define K4_SMEM ((32768 + 32 * ASTR + 64) * 4)

__global__ __launch_bounds__(256) void k_agg_gemm(
    const float* __restrict__ msg, const float* __restrict__ W,
    const float* __restrict__ bias, float* __restrict__ out,
    int N, int nTiles)
{
    extern __shared__ float sm[];
    float* Wsm = sm;                      // 32768 floats
    float* A   = sm + 32768;              // 32*520
    float* bsm = sm + 32768 + 32 * ASTR;  // 64
    const int tid = threadIdx.x;
    const int lane = tid & 31, wid = tid >> 5;

    for (int i = tid; i < 8192; i += 256) ((float4*)Wsm)[i] = ((const float4*)W)[i];
    if (tid < 64) bsm[tid] = bias[tid];
    __syncthreads();

    for (int tile = blockIdx.x; tile < nTiles; tile += gridDim.x) {
        const int n0 = tile * 32;

        // ---- gather: warp handles 4 nodes sequentially ----
        for (int q = 0; q < 4; ++q) {
            const int nl = wid * 4 + q;
            const int nn = n0 + nl;
            float acc[16];
#pragma unroll
            for (int i = 0; i < 16; ++i) acc[i] = 0.f;
            if (nn < N) {
                const int s = g_off[nn], eend = g_off[nn + 1];
                for (int p0 = s; p0 < eend; p0 += 32) {
                    int myE = (p0 + lane < eend) ? g_sorted[p0 + lane] : 0;
                    int cnt = min(32, eend - p0);
                    int eid = __shfl_sync(0xffffffffu, myE, 0);
                    float2 mc = ((const float2*)msg)[(long)eid * 32 + lane];
                    float4 wa = ((const float4*)g_w)[(long)eid * 2];
                    float4 wb = ((const float4*)g_w)[(long)eid * 2 + 1];
                    for (int j = 0; j < cnt; ++j) {
                        float2 mn = mc; float4 wan = wa, wbn = wb;
                        if (j + 1 < cnt) {
                            int e2 = __shfl_sync(0xffffffffu, myE, j + 1);
                            mn  = ((const float2*)msg)[(long)e2 * 32 + lane];
                            wan = ((const float4*)g_w)[(long)e2 * 2];
                            wbn = ((const float4*)g_w)[(long)e2 * 2 + 1];
                        }
                        acc[0]  = fmaf(wa.x, mc.x, acc[0]);
                        acc[1]  = fmaf(wa.x, mc.y, acc[1]);
                        acc[2]  = fmaf(wa.y, mc.x, acc[2]);
                        acc[3]  = fmaf(wa.y, mc.y, acc[3]);
                        acc[4]  = fmaf(wa.z, mc.x, acc[4]);
                        acc[5]  = fmaf(wa.z, mc.y, acc[5]);
                        acc[6]  = fmaf(wa.w, mc.x, acc[6]);
                        acc[7]  = fmaf(wa.w, mc.y, acc[7]);
                        acc[8]  = fmaf(wb.x, mc.x, acc[8]);
                        acc[9]  = fmaf(wb.x, mc.y, acc[9]);
                        acc[10] = fmaf(wb.y, mc.x, acc[10]);
                        acc[11] = fmaf(wb.y, mc.y, acc[11]);
                        acc[12] = fmaf(wb.z, mc.x, acc[12]);
                        acc[13] = fmaf(wb.z, mc.y, acc[13]);
                        acc[14] = fmaf(wb.w, mc.x, acc[14]);
                        acc[15] = fmaf(wb.w, mc.y, acc[15]);
                        mc = mn; wa = wan; wb = wbn;
                    }
                }
            }
            float2* arow = (float2*)(A + nl * ASTR);
#pragma unroll
            for (int kk = 0; kk < 8; ++kk)
                arow[kk * 32 + lane] = make_float2(acc[2 * kk], acc[2 * kk + 1]);
        }
        __syncthreads();

        // ---- GEMM: out[32,64] = A[32,512] @ Wsm[512,64] + b, leaky relu ----
        const int nl = tid >> 3;
        const int j0 = (tid & 7) * 8;
        ull c2[4] = {0ull, 0ull, 0ull, 0ull};
        const float* arow = A + nl * ASTR;
#pragma unroll 8
        for (int i = 0; i < 512; ++i) {
            float av = arow[i];
            ull av2 = packf2(av, av);
            longlong2 w01 = *(const longlong2*)(Wsm + i * 64 + j0);
            longlong2 w23 = *(const longlong2*)(Wsm + i * 64 + j0 + 4);
            c2[0] = fma2(av2, (ull)w01.x, c2[0]);
            c2[1] = fma2(av2, (ull)w01.y, c2[1]);
            c2[2] = fma2(av2, (ull)w23.x, c2[2]);
            c2[3] = fma2(av2, (ull)w23.y, c2[3]);
        }
        const int nn = n0 + nl;
        if (nn < N) {
            float y[8];
            unpackf2(c2[0], y[0], y[1]);
            unpackf2(c2[1], y[2], y[3]);
            unpackf2(c2[2], y[4], y[5]);
            unpackf2(c2[3], y[6], y[7]);
#pragma unroll
            for (int jj = 0; jj < 8; ++jj) {
                float v = y[jj] + bsm[j0 + jj];
                y[jj] = (v >= 0.f) ? v : 0.01f * v;
            }
            float4* o4 = (float4*)(out + (long)nn * 64 + j0);
            o4[0] = make_float4(y[0], y[1], y[2], y[3]);
            o4[1] = make_float4(y[4], y[5], y[6], y[7]);
        }
        __syncthreads();
    }
}

// ============================================================================
// launch
// ============================================================================
extern "C" void kernel_launch(void* const* d_in, const int* in_sizes, int n_in,
                              void* d_out, int out_size)
{
    const float* msg = (const float*)d_in[0];
    // d_in[1] = x_i (unused by reference)
    const float* xj  = (const float*)d_in[2];
    const float* eij = (const float*)d_in[3];
    const int*   idx = (const int*)d_in[4];
    // d_in[5] = num_nodes (scalar, unused; derived from out_size)
    const float* kc  = (const float*)d_in[6];
    const float* W   = (const float*)d_in[7];
    const float* b   = (const float*)d_in[8];
    float* out = (float*)d_out;

    const int E = in_sizes[0] / 64;
    const int N = out_size / 64;

    void* degp = nullptr;
    cudaGetSymbolAddress(&degp, g_deg);
    cudaMemsetAsync(degp, 0, (size_t)N * sizeof(int), 0);

    cudaFuncSetAttribute(k_weights, cudaFuncAttributeMaxDynamicSharedMemorySize, K1_SMEM);
    cudaFuncSetAttribute(k_agg_gemm, cudaFuncAttributeMaxDynamicSharedMemorySize, K4_SMEM);

    int eb = (E + 255) / 256;
    k_weights<<<eb, 256, K1_SMEM>>>(xj, eij, idx, kc, E);
    k_scan<<<1, 1024>>>(N);
    k_scatter<<<eb, 256>>>(idx, E);

    int sms = 148;
    cudaDeviceGetAttribute(&sms, cudaDevAttrMultiProcessorCount, 0);
    int nTiles = (N + 31) / 32;
    int grid = sms < nTiles ? sms : nTiles;
    k_agg_gemm<<<grid, 256, K4_SMEM>>>(msg, W, b, out, N, nTiles);
}

// round 2
// speedup vs baseline: 2.1512x; 2.1512x over previous
#include <cuda_runtime.h>
#include <cstdint>

#define D_IN 64
#define D_OUT 64
#define EMAX 400000
#define NMAX 50000

typedef unsigned long long ull;

// ---------------- scratch -----------------------------------------------------
__device__ float g_w[EMAX * 8];
__device__ int   g_deg[NMAX];
__device__ int   g_off[NMAX + 1];
__device__ int   g_cur[NMAX];
__device__ int   g_sorted[EMAX];

// ---------------- packed f32x2 helpers ----------------------------------------
__device__ __forceinline__ ull fma2(ull a, ull b, ull c) {
    ull d;
    asm("fma.rn.f32x2 %0, %1, %2, %3;" : "=l"(d) : "l"(a), "l"(b), "l"(c));
    return d;
}
__device__ __forceinline__ ull packf2(float lo, float hi) {
    ull r;
    asm("mov.b64 %0, {%1, %2};" : "=l"(r)
        : "r"(__float_as_uint(lo)), "r"(__float_as_uint(hi)));
    return r;
}
__device__ __forceinline__ void unpackf2(ull v, float& lo, float& hi) {
    unsigned a, b;
    asm("mov.b64 {%0, %1}, %2;" : "=r"(a), "=r"(b) : "l"(v));
    lo = __uint_as_float(a); hi = __uint_as_float(b);
}

// ============================================================================
// K1: per-edge cluster weights w[E,8] + degree histogram  (unchanged math)
// ============================================================================
#define SXS 257
#define K1_SMEM ((2048 + 64 * SXS + 32) * 4)

__global__ __launch_bounds__(256) void k_weights(
    const float* __restrict__ xj, const float* __restrict__ eij,
    const int* __restrict__ index, const float* __restrict__ kc, int E)
{
    extern __shared__ float sm[];
    float* ksm   = sm;
    float* sx    = sm + 2048;
    float* knorm = sm + 2048 + 64 * SXS;
    const int tid = threadIdx.x;

    for (int i = tid; i < 2048; i += 256) {
        int c = i >> 6, d = i & 63;
        ksm[d * 32 + c] = kc[i];
    }
    __syncthreads();
    if (tid < 32) {
        float s = 0.f;
        for (int d = 0; d < 64; ++d) { float v = ksm[d * 32 + tid]; s = fmaf(v, v, s); }
        knorm[tid] = s;
    }

    const int e0 = blockIdx.x * 256;
    const float4* xj4 = (const float4*)xj;
    const float4* ei4 = (const float4*)eij;
    const long base4 = (long)e0 * 16;
#pragma unroll
    for (int i = 0; i < 16; ++i) {
        int f = i * 256 + tid;
        int e = f >> 4, dq = f & 15;
        float4 a = make_float4(0.f, 0.f, 0.f, 0.f);
        if (e0 + e < E) {
            float4 xa = xj4[base4 + f];
            float4 xb = ei4[base4 + f];
            a.x = xa.x + xb.x; a.y = xa.y + xb.y; a.z = xa.z + xb.z; a.w = xa.w + xb.w;
        }
        sx[(dq * 4 + 0) * SXS + e] = a.x;
        sx[(dq * 4 + 1) * SXS + e] = a.y;
        sx[(dq * 4 + 2) * SXS + e] = a.z;
        sx[(dq * 4 + 3) * SXS + e] = a.w;
    }
    __syncthreads();

    const int e = e0 + tid;
    if (e >= E) return;

    ull acc[16];
#pragma unroll
    for (int i = 0; i < 16; ++i) acc[i] = 0ull;
    float xn = 0.f;

#pragma unroll 4
    for (int d = 0; d < 64; ++d) {
        float xv = sx[d * SXS + tid];
        xn = fmaf(xv, xv, xn);
        ull xv2 = packf2(xv, xv);
        const longlong2* kr = (const longlong2*)(ksm + d * 32);
#pragma unroll
        for (int p = 0; p < 8; ++p) {
            longlong2 kk = kr[p];
            acc[2 * p]     = fma2(xv2, (ull)kk.x, acc[2 * p]);
            acc[2 * p + 1] = fma2(xv2, (ull)kk.y, acc[2 * p + 1]);
        }
    }

    float t[32];
#pragma unroll
    for (int p = 0; p < 16; ++p) {
        float lo, hi;
        unpackf2(acc[p], lo, hi);
        int c = 2 * p;
        float dist = fmaxf(knorm[c] + xn - 2.f * lo, 0.f);
        t[c] = __frcp_rn(1.f + dist);
        c = 2 * p + 1;
        dist = fmaxf(knorm[c] + xn - 2.f * hi, 0.f);
        t[c] = __frcp_rn(1.f + dist);
    }

    float m[8];
#pragma unroll
    for (int kk = 0; kk < 8; ++kk) m[kk] = 0.f;
#pragma unroll
    for (int h = 0; h < 4; ++h) {
        float hs = 0.f;
#pragma unroll
        for (int kk = 0; kk < 8; ++kk) hs += t[h * 8 + kk];
        float inv = __frcp_rn(hs);
#pragma unroll
        for (int kk = 0; kk < 8; ++kk) m[kk] = fmaf(t[h * 8 + kk], inv, m[kk]);
    }
    float mx = -1e30f;
#pragma unroll
    for (int kk = 0; kk < 8; ++kk) { m[kk] *= 2.5f; mx = fmaxf(mx, m[kk]); }
    float se = 0.f;
    float ex[8];
#pragma unroll
    for (int kk = 0; kk < 8; ++kk) { ex[kk] = __expf(m[kk] - mx); se += ex[kk]; }
    float inv = __frcp_rn(se);

    float4* wout = (float4*)g_w;
    wout[e * 2]     = make_float4(ex[0] * inv, ex[1] * inv, ex[2] * inv, ex[3] * inv);
    wout[e * 2 + 1] = make_float4(ex[4] * inv, ex[5] * inv, ex[6] * inv, ex[7] * inv);

    atomicAdd(&g_deg[index[e]], 1);
}

// ============================================================================
// K2: single-block exclusive scan, 4 elems/thread (13 iters for N=50000)
// ============================================================================
__global__ void k_scan(int N)
{
    __shared__ int wsum[32];
    __shared__ int carry;
    const int tid = threadIdx.x;
    const int lane = tid & 31, wid = tid >> 5;
    if (tid == 0) carry = 0;
    __syncthreads();
    const int iters = (N + 4095) / 4096;
    for (int it = 0; it < iters; ++it) {
        int i0 = it * 4096 + tid * 4;
        int v0 = (i0 + 0 < N) ? g_deg[i0 + 0] : 0;
        int v1 = (i0 + 1 < N) ? g_deg[i0 + 1] : 0;
        int v2 = (i0 + 2 < N) ? g_deg[i0 + 2] : 0;
        int v3 = (i0 + 3 < N) ? g_deg[i0 + 3] : 0;
        int s = v0 + v1 + v2 + v3;
        int x = s;
#pragma unroll
        for (int o = 1; o < 32; o <<= 1) {
            int y = __shfl_up_sync(0xffffffffu, x, o);
            if (lane >= o) x += y;
        }
        if (lane == 31) wsum[wid] = x;
        __syncthreads();
        if (wid == 0) {
            int ss = wsum[lane];
            int xs = ss;
#pragma unroll
            for (int o = 1; o < 32; o <<= 1) {
                int y = __shfl_up_sync(0xffffffffu, xs, o);
                if (lane >= o) xs += y;
            }
            wsum[lane] = xs - ss;
        }
        __syncthreads();
        int p = carry + (x - s) + wsum[wid];
        if (i0 + 0 < N) { g_off[i0 + 0] = p; g_cur[i0 + 0] = p; } p += v0;
        if (i0 + 1 < N) { g_off[i0 + 1] = p; g_cur[i0 + 1] = p; } p += v1;
        if (i0 + 2 < N) { g_off[i0 + 2] = p; g_cur[i0 + 2] = p; } p += v2;
        if (i0 + 3 < N) { g_off[i0 + 3] = p; g_cur[i0 + 3] = p; }
        __syncthreads();
        if (tid == 1023) carry += x + wsum[31];
        __syncthreads();
    }
    if (tid == 0) g_off[N] = carry;
}

// ============================================================================
// K3: scatter edge ids into CSR order
// ============================================================================
__global__ void k_scatter(const int* __restrict__ index, int E)
{
    int e = blockIdx.x * 256 + threadIdx.x;
    if (e < E) {
        int pos = atomicAdd(&g_cur[index[e]], 1);
        g_sorted[pos] = e;
    }
}

// ============================================================================
// K4: gather (MLP=8 prefetch) + register-tiled GEMM, persistent blocks
// smem: Wsm[512*64] + A[32][520] + bias[64]
// ============================================================================
#define ASTR 520
#define K4_SMEM ((32768 + 32 * ASTR + 64) * 4)

__global__ __launch_bounds__(256, 1) void k_agg_gemm(
    const float* __restrict__ msg, const float* __restrict__ W,
    const float* __restrict__ bias, float* __restrict__ out,
    int N, int nTiles)
{
    extern __shared__ float sm[];
    float* Wsm = sm;                      // 32768 floats
    float* A   = sm + 32768;              // 32*520
    float* bsm = sm + 32768 + 32 * ASTR;  // 64
    const int tid = threadIdx.x;
    const int lane = tid & 31, wid = tid >> 5;
    const unsigned FULL = 0xffffffffu;

    for (int i = tid; i < 8192; i += 256) ((float4*)Wsm)[i] = ((const float4*)W)[i];
    if (tid < 64) bsm[tid] = bias[tid];
    __syncthreads();

    const ull* msg2 = (const ull*)msg;       // float2 rows of 32
    const ull* gw2  = (const ull*)g_w;       // 4 ull per edge

    for (int tile = blockIdx.x; tile < nTiles; tile += gridDim.x) {
        const int n0 = tile * 32;

        // ---- gather: warp handles 4 nodes; 8-edge prefetch groups (MLP=8) ----
        for (int q = 0; q < 4; ++q) {
            const int nl = wid * 4 + q;
            const int nn = n0 + nl;
            ull acc2[8];
#pragma unroll
            for (int i = 0; i < 8; ++i) acc2[i] = 0ull;
            if (nn < N) {
                const int s = g_off[nn], eend = g_off[nn + 1];
                for (int p0 = s; p0 < eend; p0 += 32) {
                    const int cnt = min(32, eend - p0);
                    int myE = (lane < cnt) ? g_sorted[p0 + lane] : 0;
                    for (int j0 = 0; j0 < cnt; j0 += 8) {
                        ull m2[8], w01[8], w23[8], w45[8], w67[8];
#pragma unroll
                        for (int t = 0; t < 8; ++t) {
                            int e = __shfl_sync(FULL, myE, (j0 + t) & 31);
                            m2[t] = msg2[(long)e * 32 + lane];
                            const ull* wp = gw2 + (long)e * 4;
                            w01[t] = wp[0]; w23[t] = wp[1];
                            w45[t] = wp[2]; w67[t] = wp[3];
                        }
                        const int jn = min(8, cnt - j0);
#pragma unroll
                        for (int t = 0; t < 8; ++t) {
                            if (t < jn) {
                                float mx, my;
                                unpackf2(m2[t], mx, my);
                                ull mxx = packf2(mx, mx);
                                ull myy = packf2(my, my);
                                acc2[0] = fma2(w01[t], mxx, acc2[0]);
                                acc2[1] = fma2(w01[t], myy, acc2[1]);
                                acc2[2] = fma2(w23[t], mxx, acc2[2]);
                                acc2[3] = fma2(w23[t], myy, acc2[3]);
                                acc2[4] = fma2(w45[t], mxx, acc2[4]);
                                acc2[5] = fma2(w45[t], myy, acc2[5]);
                                acc2[6] = fma2(w67[t], mxx, acc2[6]);
                                acc2[7] = fma2(w67[t], myy, acc2[7]);
                            }
                        }
                    }
                }
            }
            // A[nl][k*64 + 2*lane + c];  acc2[kp*2+c] = (k=2kp, k=2kp+1)
            float* arow = A + nl * ASTR;
#pragma unroll
            for (int kp = 0; kp < 4; ++kp) {
#pragma unroll
                for (int c = 0; c < 2; ++c) {
                    float a, b;
                    unpackf2(acc2[kp * 2 + c], a, b);
                    arow[(2 * kp) * 64 + 2 * lane + c]     = a;
                    arow[(2 * kp + 1) * 64 + 2 * lane + c] = b;
                }
            }
        }
        __syncthreads();

        // ---- GEMM: out[32,64] = A[32,512] @ Wsm[512,64] + b, leaky relu ----
        // thread tile: 2 rows x 4 cols; rowgrp = tid>>4 (0..15), colgrp = tid&15
        const int rg = tid >> 4;
        const int cg = tid & 15;
        const int r0 = rg * 2;
        const int c0 = cg * 4;
        ull cacc[4] = {0ull, 0ull, 0ull, 0ull};  // [row][colpair]
        const float* a0p = A + (r0 + 0) * ASTR;
        const float* a1p = A + (r0 + 1) * ASTR;
#pragma unroll 4
        for (int i = 0; i < 512; i += 4) {
            float4 a0 = *(const float4*)(a0p + i);
            float4 a1 = *(const float4*)(a1p + i);
            float a0v[4] = {a0.x, a0.y, a0.z, a0.w};
            float a1v[4] = {a1.x, a1.y, a1.z, a1.w};
#pragma unroll
            for (int t = 0; t < 4; ++t) {
                float4 wv = *(const float4*)(Wsm + (i + t) * 64 + c0);
                ull wlo = packf2(wv.x, wv.y);
                ull whi = packf2(wv.z, wv.w);
                ull av0 = packf2(a0v[t], a0v[t]);
                ull av1 = packf2(a1v[t], a1v[t]);
                cacc[0] = fma2(av0, wlo, cacc[0]);
                cacc[1] = fma2(av0, whi, cacc[1]);
                cacc[2] = fma2(av1, wlo, cacc[2]);
                cacc[3] = fma2(av1, whi, cacc[3]);
            }
        }
#pragma unroll
        for (int r = 0; r < 2; ++r) {
            const int nn = n0 + r0 + r;
            if (nn < N) {
                float y[4];
                unpackf2(cacc[r * 2 + 0], y[0], y[1]);
                unpackf2(cacc[r * 2 + 1], y[2], y[3]);
#pragma unroll
                for (int jj = 0; jj < 4; ++jj) {
                    float v = y[jj] + bsm[c0 + jj];
                    y[jj] = (v >= 0.f) ? v : 0.01f * v;
                }
                *(float4*)(out + (long)nn * 64 + c0) = make_float4(y[0], y[1], y[2], y[3]);
            }
        }
        __syncthreads();
    }
}

// ============================================================================
// launch
// ============================================================================
extern "C" void kernel_launch(void* const* d_in, const int* in_sizes, int n_in,
                              void* d_out, int out_size)
{
    const float* msg = (const float*)d_in[0];
    const float* xj  = (const float*)d_in[2];
    const float* eij = (const float*)d_in[3];
    const int*   idx = (const int*)d_in[4];
    const float* kc  = (const float*)d_in[6];
    const float* W   = (const float*)d_in[7];
    const float* b   = (const float*)d_in[8];
    float* out = (float*)d_out;

    const int E = in_sizes[0] / 64;
    const int N = out_size / 64;

    void* degp = nullptr;
    cudaGetSymbolAddress(&degp, g_deg);
    cudaMemsetAsync(degp, 0, (size_t)N * sizeof(int), 0);

    cudaFuncSetAttribute(k_weights, cudaFuncAttributeMaxDynamicSharedMemorySize, K1_SMEM);
    cudaFuncSetAttribute(k_agg_gemm, cudaFuncAttributeMaxDynamicSharedMemorySize, K4_SMEM);

    int eb = (E + 255) / 256;
    k_weights<<<eb, 256, K1_SMEM>>>(xj, eij, idx, kc, E);
    k_scan<<<1, 1024>>>(N);
    k_scatter<<<eb, 256>>>(idx, E);

    int sms = 148;
    cudaDeviceGetAttribute(&sms, cudaDevAttrMultiProcessorCount, 0);
    int nTiles = (N + 31) / 32;
    int grid = sms < nTiles ? sms : nTiles;
    k_agg_gemm<<<grid, 256, K4_SMEM>>>(msg, W, b, out, N, nTiles);
}

// round 3
// speedup vs baseline: 2.3346x; 1.0853x over previous
#include <cuda_runtime.h>
#include <cstdint>

#define D_IN 64
#define D_OUT 64
#define EMAX 400000
#define NMAX 50000

typedef unsigned long long ull;

// ---------------- scratch -----------------------------------------------------
__device__ float g_w[EMAX * 8];
__device__ int   g_deg[NMAX];
__device__ int   g_off[NMAX + 1];
__device__ int   g_cur[NMAX];
__device__ int   g_sorted[EMAX];
__device__ float g_part[2][NMAX * 64];

// ---------------- packed f32x2 helpers ----------------------------------------
__device__ __forceinline__ ull fma2(ull a, ull b, ull c) {
    ull d;
    asm("fma.rn.f32x2 %0, %1, %2, %3;" : "=l"(d) : "l"(a), "l"(b), "l"(c));
    return d;
}
__device__ __forceinline__ ull packf2(float lo, float hi) {
    ull r;
    asm("mov.b64 %0, {%1, %2};" : "=l"(r)
        : "r"(__float_as_uint(lo)), "r"(__float_as_uint(hi)));
    return r;
}
__device__ __forceinline__ void unpackf2(ull v, float& lo, float& hi) {
    unsigned a, b;
    asm("mov.b64 {%0, %1}, %2;" : "=r"(a), "=r"(b) : "l"(v));
    lo = __uint_as_float(a); hi = __uint_as_float(b);
}

// ============================================================================
// K1: per-edge cluster weights w[E,8] + degree histogram
// ============================================================================
#define SXS 257
#define K1_SMEM ((2048 + 64 * SXS + 32) * 4)

__global__ __launch_bounds__(256) void k_weights(
    const float* __restrict__ xj, const float* __restrict__ eij,
    const int* __restrict__ index, const float* __restrict__ kc, int E)
{
    extern __shared__ float sm[];
    float* ksm   = sm;
    float* sx    = sm + 2048;
    float* knorm = sm + 2048 + 64 * SXS;
    const int tid = threadIdx.x;

    for (int i = tid; i < 2048; i += 256) {
        int c = i >> 6, d = i & 63;
        ksm[d * 32 + c] = kc[i];
    }
    __syncthreads();
    if (tid < 32) {
        float s = 0.f;
        for (int d = 0; d < 64; ++d) { float v = ksm[d * 32 + tid]; s = fmaf(v, v, s); }
        knorm[tid] = s;
    }

    const int e0 = blockIdx.x * 256;
    const float4* xj4 = (const float4*)xj;
    const float4* ei4 = (const float4*)eij;
    const long base4 = (long)e0 * 16;
#pragma unroll
    for (int i = 0; i < 16; ++i) {
        int f = i * 256 + tid;
        int e = f >> 4, dq = f & 15;
        float4 a = make_float4(0.f, 0.f, 0.f, 0.f);
        if (e0 + e < E) {
            float4 xa = xj4[base4 + f];
            float4 xb = ei4[base4 + f];
            a.x = xa.x + xb.x; a.y = xa.y + xb.y; a.z = xa.z + xb.z; a.w = xa.w + xb.w;
        }
        sx[(dq * 4 + 0) * SXS + e] = a.x;
        sx[(dq * 4 + 1) * SXS + e] = a.y;
        sx[(dq * 4 + 2) * SXS + e] = a.z;
        sx[(dq * 4 + 3) * SXS + e] = a.w;
    }
    __syncthreads();

    const int e = e0 + tid;
    if (e >= E) return;

    ull acc[16];
#pragma unroll
    for (int i = 0; i < 16; ++i) acc[i] = 0ull;
    float xn = 0.f;

#pragma unroll 4
    for (int d = 0; d < 64; ++d) {
        float xv = sx[d * SXS + tid];
        xn = fmaf(xv, xv, xn);
        ull xv2 = packf2(xv, xv);
        const longlong2* kr = (const longlong2*)(ksm + d * 32);
#pragma unroll
        for (int p = 0; p < 8; ++p) {
            longlong2 kk = kr[p];
            acc[2 * p]     = fma2(xv2, (ull)kk.x, acc[2 * p]);
            acc[2 * p + 1] = fma2(xv2, (ull)kk.y, acc[2 * p + 1]);
        }
    }

    float t[32];
#pragma unroll
    for (int p = 0; p < 16; ++p) {
        float lo, hi;
        unpackf2(acc[p], lo, hi);
        int c = 2 * p;
        float dist = fmaxf(knorm[c] + xn - 2.f * lo, 0.f);
        t[c] = __frcp_rn(1.f + dist);
        c = 2 * p + 1;
        dist = fmaxf(knorm[c] + xn - 2.f * hi, 0.f);
        t[c] = __frcp_rn(1.f + dist);
    }

    float m[8];
#pragma unroll
    for (int kk = 0; kk < 8; ++kk) m[kk] = 0.f;
#pragma unroll
    for (int h = 0; h < 4; ++h) {
        float hs = 0.f;
#pragma unroll
        for (int kk = 0; kk < 8; ++kk) hs += t[h * 8 + kk];
        float inv = __frcp_rn(hs);
#pragma unroll
        for (int kk = 0; kk < 8; ++kk) m[kk] = fmaf(t[h * 8 + kk], inv, m[kk]);
    }
    float mx = -1e30f;
#pragma unroll
    for (int kk = 0; kk < 8; ++kk) { m[kk] *= 2.5f; mx = fmaxf(mx, m[kk]); }
    float se = 0.f;
    float ex[8];
#pragma unroll
    for (int kk = 0; kk < 8; ++kk) { ex[kk] = __expf(m[kk] - mx); se += ex[kk]; }
    float inv = __frcp_rn(se);

    float4* wout = (float4*)g_w;
    wout[e * 2]     = make_float4(ex[0] * inv, ex[1] * inv, ex[2] * inv, ex[3] * inv);
    wout[e * 2 + 1] = make_float4(ex[4] * inv, ex[5] * inv, ex[6] * inv, ex[7] * inv);

    atomicAdd(&g_deg[index[e]], 1);
}

// ============================================================================
// K2: single-block exclusive scan, 4 elems/thread
// ============================================================================
__global__ void k_scan(int N)
{
    __shared__ int wsum[32];
    __shared__ int carry;
    const int tid = threadIdx.x;
    const int lane = tid & 31, wid = tid >> 5;
    if (tid == 0) carry = 0;
    __syncthreads();
    const int iters = (N + 4095) / 4096;
    for (int it = 0; it < iters; ++it) {
        int i0 = it * 4096 + tid * 4;
        int v0 = (i0 + 0 < N) ? g_deg[i0 + 0] : 0;
        int v1 = (i0 + 1 < N) ? g_deg[i0 + 1] : 0;
        int v2 = (i0 + 2 < N) ? g_deg[i0 + 2] : 0;
        int v3 = (i0 + 3 < N) ? g_deg[i0 + 3] : 0;
        int s = v0 + v1 + v2 + v3;
        int x = s;
#pragma unroll
        for (int o = 1; o < 32; o <<= 1) {
            int y = __shfl_up_sync(0xffffffffu, x, o);
            if (lane >= o) x += y;
        }
        if (lane == 31) wsum[wid] = x;
        __syncthreads();
        if (wid == 0) {
            int ss = wsum[lane];
            int xs = ss;
#pragma unroll
            for (int o = 1; o < 32; o <<= 1) {
                int y = __shfl_up_sync(0xffffffffu, xs, o);
                if (lane >= o) xs += y;
            }
            wsum[lane] = xs - ss;
        }
        __syncthreads();
        int p = carry + (x - s) + wsum[wid];
        if (i0 + 0 < N) { g_off[i0 + 0] = p; g_cur[i0 + 0] = p; } p += v0;
        if (i0 + 1 < N) { g_off[i0 + 1] = p; g_cur[i0 + 1] = p; } p += v1;
        if (i0 + 2 < N) { g_off[i0 + 2] = p; g_cur[i0 + 2] = p; } p += v2;
        if (i0 + 3 < N) { g_off[i0 + 3] = p; g_cur[i0 + 3] = p; }
        __syncthreads();
        if (tid == 1023) carry += x + wsum[31];
        __syncthreads();
    }
    if (tid == 0) g_off[N] = carry;
}

// ============================================================================
// K3: scatter edge ids into CSR order
// ============================================================================
__global__ void k_scatter(const int* __restrict__ index, int E)
{
    int e = blockIdx.x * 256 + threadIdx.x;
    if (e < E) {
        int pos = atomicAdd(&g_cur[index[e]], 1);
        g_sorted[pos] = e;
    }
}

// ============================================================================
// K4: k-split gather + GEMM. Each block handles one k-half (256 of 512).
// Block pair (2t, 2t+1) processes the same node tile -> msg L2 reuse.
// smem: Whalf[256*64] (64KB) + A[32][260] (33.3KB)  => 2 blocks/SM, 16 warps.
// ============================================================================
#define AH 260
#define K4_SMEM ((16384 + 32 * AH) * 4)

__global__ __launch_bounds__(256, 2) void k_agg_gemm(
    const float* __restrict__ msg, const float* __restrict__ W, int N, int nTiles)
{
    extern __shared__ float sm[];
    float* Wsm = sm;             // 16384 floats (this half's 256 rows of W)
    float* A   = sm + 16384;     // 32 * 260
    const int tid = threadIdx.x;
    const int lane = tid & 31, wid = tid >> 5;
    const unsigned FULL = 0xffffffffu;
    const int half = blockIdx.x & 1;
    const int pairId = blockIdx.x >> 1;
    const int nPairs = gridDim.x >> 1;

    // load this half of W (rows half*256 .. half*256+255)
    const float4* Wsrc = (const float4*)(W + half * 256 * 64);
    for (int i = tid; i < 4096; i += 256) ((float4*)Wsm)[i] = Wsrc[i];
    __syncthreads();

    const ull* msg2 = (const ull*)msg;                 // float2 per lane
    const longlong2* gw4 = (const longlong2*)g_w;      // 2 x longlong2 per edge
    float* part = g_part[half];

    for (int tile = pairId; tile < nTiles; tile += nPairs) {
        const int n0 = tile * 32;

        // ---- per-warp: preload offsets for its 4 nodes (1 LDG + shfl) ----
        const int nb = n0 + wid * 4;
        int offv = 0;
        if (lane < 5) {
            int idx = nb + lane;
            if (idx > N) idx = N;
            offv = g_off[idx];
        }
        int s_q[4], d_q[4];
#pragma unroll
        for (int q = 0; q < 4; ++q) {
            int a = __shfl_sync(FULL, offv, q);
            int b = __shfl_sync(FULL, offv, q + 1);
            if (nb + q >= N) { a = 0; b = 0; }
            s_q[q] = a; d_q[q] = b - a;
        }
        // ---- preload first 32 edge ids of each node (4 independent LDGs) ----
        int ids[4];
#pragma unroll
        for (int q = 0; q < 4; ++q)
            ids[q] = (lane < d_q[q]) ? g_sorted[s_q[q] + lane] : 0;

        // ---- gather ----
        for (int q = 0; q < 4; ++q) {
            const int nl = wid * 4 + q;
            ull acc2[4] = {0ull, 0ull, 0ull, 0ull};
            const int deg = d_q[q];
            int myE = ids[q];
            for (int p0 = 0; p0 < deg; p0 += 32) {
                if (p0 > 0) myE = (lane < deg - p0) ? g_sorted[s_q[q] + p0 + lane] : 0;
                const int cnt = min(32, deg - p0);
                for (int j0 = 0; j0 < cnt; j0 += 8) {
                    ull m2[8]; longlong2 ww[8];
#pragma unroll
                    for (int t = 0; t < 8; ++t) {
                        int e = __shfl_sync(FULL, myE, (j0 + t) & 31);
                        m2[t] = msg2[(long)e * 32 + lane];
                        ww[t] = gw4[(long)e * 2 + half];
                    }
                    const int jn = min(8, cnt - j0);
#pragma unroll
                    for (int t = 0; t < 8; ++t) {
                        if (t < jn) {
                            float mx, my;
                            unpackf2(m2[t], mx, my);
                            ull mxx = packf2(mx, mx);
                            ull myy = packf2(my, my);
                            acc2[0] = fma2((ull)ww[t].x, mxx, acc2[0]);
                            acc2[1] = fma2((ull)ww[t].x, myy, acc2[1]);
                            acc2[2] = fma2((ull)ww[t].y, mxx, acc2[2]);
                            acc2[3] = fma2((ull)ww[t].y, myy, acc2[3]);
                        }
                    }
                }
            }
            // A[nl][k*64 + 2*lane + c], k = local cluster 0..3
            float* arow = A + nl * AH;
#pragma unroll
            for (int kp = 0; kp < 2; ++kp) {
#pragma unroll
                for (int c = 0; c < 2; ++c) {
                    float a, b;
                    unpackf2(acc2[kp * 2 + c], a, b);
                    arow[(2 * kp) * 64 + 2 * lane + c]     = a;
                    arow[(2 * kp + 1) * 64 + 2 * lane + c] = b;
                }
            }
        }
        __syncthreads();

        // ---- GEMM: part[32,64] = A[32,256] @ Wsm[256,64] ----
        const int rg = tid >> 4;
        const int cg = tid & 15;
        const int r0 = rg * 2;
        const int c0 = cg * 4;
        ull cacc[4] = {0ull, 0ull, 0ull, 0ull};
        const float* a0p = A + (r0 + 0) * AH;
        const float* a1p = A + (r0 + 1) * AH;
#pragma unroll 4
        for (int i = 0; i < 256; i += 4) {
            float4 a0 = *(const float4*)(a0p + i);
            float4 a1 = *(const float4*)(a1p + i);
            float a0v[4] = {a0.x, a0.y, a0.z, a0.w};
            float a1v[4] = {a1.x, a1.y, a1.z, a1.w};
#pragma unroll
            for (int t = 0; t < 4; ++t) {
                float4 wv = *(const float4*)(Wsm + (i + t) * 64 + c0);
                ull wlo = packf2(wv.x, wv.y);
                ull whi = packf2(wv.z, wv.w);
                ull av0 = packf2(a0v[t], a0v[t]);
                ull av1 = packf2(a1v[t], a1v[t]);
                cacc[0] = fma2(av0, wlo, cacc[0]);
                cacc[1] = fma2(av0, whi, cacc[1]);
                cacc[2] = fma2(av1, wlo, cacc[2]);
                cacc[3] = fma2(av1, whi, cacc[3]);
            }
        }
#pragma unroll
        for (int r = 0; r < 2; ++r) {
            const int nn = n0 + r0 + r;
            if (nn < N) {
                float y[4];
                unpackf2(cacc[r * 2 + 0], y[0], y[1]);
                unpackf2(cacc[r * 2 + 1], y[2], y[3]);
                *(float4*)(part + (long)nn * 64 + c0) = make_float4(y[0], y[1], y[2], y[3]);
            }
        }
        __syncthreads();
    }
}

// ============================================================================
// K5: combine halves + bias + leaky relu
// ============================================================================
__global__ __launch_bounds__(256) void k_combine(
    const float* __restrict__ bias, float* __restrict__ out, int n4)
{
    int i = blockIdx.x * 256 + threadIdx.x;
    if (i >= n4) return;
    const float4* p0 = (const float4*)g_part[0];
    const float4* p1 = (const float4*)g_part[1];
    float4 a = p0[i], b = p1[i];
    float4 bb = ((const float4*)bias)[i & 15];
    float y[4] = {a.x + b.x + bb.x, a.y + b.y + bb.y,
                  a.z + b.z + bb.z, a.w + b.w + bb.w};
#pragma unroll
    for (int j = 0; j < 4; ++j) y[j] = (y[j] >= 0.f) ? y[j] : 0.01f * y[j];
    ((float4*)out)[i] = make_float4(y[0], y[1], y[2], y[3]);
}

// ============================================================================
// launch
// ============================================================================
extern "C" void kernel_launch(void* const* d_in, const int* in_sizes, int n_in,
                              void* d_out, int out_size)
{
    const float* msg = (const float*)d_in[0];
    const float* xj  = (const float*)d_in[2];
    const float* eij = (const float*)d_in[3];
    const int*   idx = (const int*)d_in[4];
    const float* kc  = (const float*)d_in[6];
    const float* W   = (const float*)d_in[7];
    const float* b   = (const float*)d_in[8];
    float* out = (float*)d_out;

    const int E = in_sizes[0] / 64;
    const int N = out_size / 64;

    void* degp = nullptr;
    cudaGetSymbolAddress(&degp, g_deg);
    cudaMemsetAsync(degp, 0, (size_t)N * sizeof(int), 0);

    cudaFuncSetAttribute(k_weights, cudaFuncAttributeMaxDynamicSharedMemorySize, K1_SMEM);
    cudaFuncSetAttribute(k_agg_gemm, cudaFuncAttributeMaxDynamicSharedMemorySize, K4_SMEM);

    int eb = (E + 255) / 256;
    k_weights<<<eb, 256, K1_SMEM>>>(xj, eij, idx, kc, E);
    k_scan<<<1, 1024>>>(N);
    k_scatter<<<eb, 256>>>(idx, E);

    int sms = 148;
    cudaDeviceGetAttribute(&sms, cudaDevAttrMultiProcessorCount, 0);
    int nTiles = (N + 31) / 32;
    int nPairs = sms < nTiles ? sms : nTiles;
    k_agg_gemm<<<2 * nPairs, 256, K4_SMEM>>>(msg, W, N, nTiles);

    int n4 = N * 16;
    k_combine<<<(n4 + 255) / 256, 256>>>(b, out, n4);
}

// round 4
// speedup vs baseline: 2.4037x; 1.0296x over previous
#include <cuda_runtime.h>
#include <cstdint>

#define D_IN 64
#define D_OUT 64
#define EMAX 400000
#define NMAX 50000

typedef unsigned long long ull;

// ---------------- scratch -----------------------------------------------------
__device__ float g_w[EMAX * 8];
__device__ int   g_deg[NMAX];
__device__ int   g_off[NMAX + 1];
__device__ int   g_cur[NMAX];
__device__ int   g_sorted[EMAX];
__device__ float g_part[2][NMAX * 64];

// ---------------- packed f32x2 helpers ----------------------------------------
__device__ __forceinline__ ull fma2(ull a, ull b, ull c) {
    ull d;
    asm("fma.rn.f32x2 %0, %1, %2, %3;" : "=l"(d) : "l"(a), "l"(b), "l"(c));
    return d;
}
__device__ __forceinline__ ull packf2(float lo, float hi) {
    ull r;
    asm("mov.b64 %0, {%1, %2};" : "=l"(r)
        : "r"(__float_as_uint(lo)), "r"(__float_as_uint(hi)));
    return r;
}
__device__ __forceinline__ void unpackf2(ull v, float& lo, float& hi) {
    unsigned a, b;
    asm("mov.b64 {%0, %1}, %2;" : "=r"(a), "=r"(b) : "l"(v));
    lo = __uint_as_float(a); hi = __uint_as_float(b);
}

// ============================================================================
// K1: per-edge cluster weights w[E,8] + degree histogram
// ============================================================================
#define SXS 257
#define K1_SMEM ((2048 + 64 * SXS + 32) * 4)

__global__ __launch_bounds__(256) void k_weights(
    const float* __restrict__ xj, const float* __restrict__ eij,
    const int* __restrict__ index, const float* __restrict__ kc, int E)
{
    extern __shared__ float sm[];
    float* ksm   = sm;
    float* sx    = sm + 2048;
    float* knorm = sm + 2048 + 64 * SXS;
    const int tid = threadIdx.x;

    for (int i = tid; i < 2048; i += 256) {
        int c = i >> 6, d = i & 63;
        ksm[d * 32 + c] = kc[i];
    }
    __syncthreads();
    if (tid < 32) {
        float s = 0.f;
        for (int d = 0; d < 64; ++d) { float v = ksm[d * 32 + tid]; s = fmaf(v, v, s); }
        knorm[tid] = s;
    }

    const int e0 = blockIdx.x * 256;
    const float4* xj4 = (const float4*)xj;
    const float4* ei4 = (const float4*)eij;
    const long base4 = (long)e0 * 16;
#pragma unroll
    for (int i = 0; i < 16; ++i) {
        int f = i * 256 + tid;
        int e = f >> 4, dq = f & 15;
        float4 a = make_float4(0.f, 0.f, 0.f, 0.f);
        if (e0 + e < E) {
            float4 xa = xj4[base4 + f];
            float4 xb = ei4[base4 + f];
            a.x = xa.x + xb.x; a.y = xa.y + xb.y; a.z = xa.z + xb.z; a.w = xa.w + xb.w;
        }
        sx[(dq * 4 + 0) * SXS + e] = a.x;
        sx[(dq * 4 + 1) * SXS + e] = a.y;
        sx[(dq * 4 + 2) * SXS + e] = a.z;
        sx[(dq * 4 + 3) * SXS + e] = a.w;
    }
    __syncthreads();

    const int e = e0 + tid;
    if (e >= E) return;

    ull acc[16];
#pragma unroll
    for (int i = 0; i < 16; ++i) acc[i] = 0ull;
    float xn = 0.f;

#pragma unroll 4
    for (int d = 0; d < 64; ++d) {
        float xv = sx[d * SXS + tid];
        xn = fmaf(xv, xv, xn);
        ull xv2 = packf2(xv, xv);
        const longlong2* kr = (const longlong2*)(ksm + d * 32);
#pragma unroll
        for (int p = 0; p < 8; ++p) {
            longlong2 kk = kr[p];
            acc[2 * p]     = fma2(xv2, (ull)kk.x, acc[2 * p]);
            acc[2 * p + 1] = fma2(xv2, (ull)kk.y, acc[2 * p + 1]);
        }
    }

    float t[32];
#pragma unroll
    for (int p = 0; p < 16; ++p) {
        float lo, hi;
        unpackf2(acc[p], lo, hi);
        int c = 2 * p;
        float dist = fmaxf(knorm[c] + xn - 2.f * lo, 0.f);
        t[c] = __frcp_rn(1.f + dist);
        c = 2 * p + 1;
        dist = fmaxf(knorm[c] + xn - 2.f * hi, 0.f);
        t[c] = __frcp_rn(1.f + dist);
    }

    float m[8];
#pragma unroll
    for (int kk = 0; kk < 8; ++kk) m[kk] = 0.f;
#pragma unroll
    for (int h = 0; h < 4; ++h) {
        float hs = 0.f;
#pragma unroll
        for (int kk = 0; kk < 8; ++kk) hs += t[h * 8 + kk];
        float inv = __frcp_rn(hs);
#pragma unroll
        for (int kk = 0; kk < 8; ++kk) m[kk] = fmaf(t[h * 8 + kk], inv, m[kk]);
    }
    float mx = -1e30f;
#pragma unroll
    for (int kk = 0; kk < 8; ++kk) { m[kk] *= 2.5f; mx = fmaxf(mx, m[kk]); }
    float se = 0.f;
    float ex[8];
#pragma unroll
    for (int kk = 0; kk < 8; ++kk) { ex[kk] = __expf(m[kk] - mx); se += ex[kk]; }
    float inv = __frcp_rn(se);

    float4* wout = (float4*)g_w;
    wout[e * 2]     = make_float4(ex[0] * inv, ex[1] * inv, ex[2] * inv, ex[3] * inv);
    wout[e * 2 + 1] = make_float4(ex[4] * inv, ex[5] * inv, ex[6] * inv, ex[7] * inv);

    atomicAdd(&g_deg[index[e]], 1);
}

// ============================================================================
// K2: single-block exclusive scan, 4 elems/thread
// ============================================================================
__global__ void k_scan(int N)
{
    __shared__ int wsum[32];
    __shared__ int carry;
    const int tid = threadIdx.x;
    const int lane = tid & 31, wid = tid >> 5;
    if (tid == 0) carry = 0;
    __syncthreads();
    const int iters = (N + 4095) / 4096;
    for (int it = 0; it < iters; ++it) {
        int i0 = it * 4096 + tid * 4;
        int v0 = (i0 + 0 < N) ? g_deg[i0 + 0] : 0;
        int v1 = (i0 + 1 < N) ? g_deg[i0 + 1] : 0;
        int v2 = (i0 + 2 < N) ? g_deg[i0 + 2] : 0;
        int v3 = (i0 + 3 < N) ? g_deg[i0 + 3] : 0;
        int s = v0 + v1 + v2 + v3;
        int x = s;
#pragma unroll
        for (int o = 1; o < 32; o <<= 1) {
            int y = __shfl_up_sync(0xffffffffu, x, o);
            if (lane >= o) x += y;
        }
        if (lane == 31) wsum[wid] = x;
        __syncthreads();
        if (wid == 0) {
            int ss = wsum[lane];
            int xs = ss;
#pragma unroll
            for (int o = 1; o < 32; o <<= 1) {
                int y = __shfl_up_sync(0xffffffffu, xs, o);
                if (lane >= o) xs += y;
            }
            wsum[lane] = xs - ss;
        }
        __syncthreads();
        int p = carry + (x - s) + wsum[wid];
        if (i0 + 0 < N) { g_off[i0 + 0] = p; g_cur[i0 + 0] = p; } p += v0;
        if (i0 + 1 < N) { g_off[i0 + 1] = p; g_cur[i0 + 1] = p; } p += v1;
        if (i0 + 2 < N) { g_off[i0 + 2] = p; g_cur[i0 + 2] = p; } p += v2;
        if (i0 + 3 < N) { g_off[i0 + 3] = p; g_cur[i0 + 3] = p; }
        __syncthreads();
        if (tid == 1023) carry += x + wsum[31];
        __syncthreads();
    }
    if (tid == 0) g_off[N] = carry;
}

// ============================================================================
// K3: scatter edge ids into CSR order
// ============================================================================
__global__ void k_scatter(const int* __restrict__ index, int E)
{
    int e = blockIdx.x * 256 + threadIdx.x;
    if (e < E) {
        int pos = atomicAdd(&g_cur[index[e]], 1);
        g_sorted[pos] = e;
    }
}

// ============================================================================
// K4: k-split gather + GEMM (i-split, 2x8 thread tile, conflict-free W reads)
// smem: Whalf[256*64] (64KB) + A[32][260] (33.3KB)  => 2 blocks/SM
// ============================================================================
#define AH 260
#define RSTR 68
#define K4_SMEM ((16384 + 32 * AH) * 4)

__global__ __launch_bounds__(256, 2) void k_agg_gemm(
    const float* __restrict__ msg, const float* __restrict__ W, int N, int nTiles)
{
    extern __shared__ float sm[];
    float* Wsm = sm;             // 16384 floats (this half's 256 rows of W)
    float* A   = sm + 16384;     // 32 * 260
    const int tid = threadIdx.x;
    const int lane = tid & 31, wid = tid >> 5;
    const unsigned FULL = 0xffffffffu;
    const int half = blockIdx.x & 1;
    const int pairId = blockIdx.x >> 1;
    const int nPairs = gridDim.x >> 1;

    const float4* Wsrc = (const float4*)(W + half * 256 * 64);
    for (int i = tid; i < 4096; i += 256) ((float4*)Wsm)[i] = Wsrc[i];
    __syncthreads();

    const ull* msg2 = (const ull*)msg;
    const longlong2* gw4 = (const longlong2*)g_w;
    float* part = g_part[half];

    // GEMM thread mapping (constant across tiles)
    const int ihalf = tid >> 7;        // i-range half
    const int t128  = tid & 127;
    const int rg = t128 >> 3;          // 0..15
    const int cg = t128 & 7;           // 0..7
    const int r0 = rg * 2;
    const int cA = cg * 4;
    const int cB = 32 + cg * 4;

    for (int tile = pairId; tile < nTiles; tile += nPairs) {
        const int n0 = tile * 32;

        // ---- per-warp: preload offsets for its 4 nodes ----
        const int nb = n0 + wid * 4;
        int offv = 0;
        if (lane < 5) {
            int idx = nb + lane;
            if (idx > N) idx = N;
            offv = g_off[idx];
        }
        int s_q[4], d_q[4];
#pragma unroll
        for (int q = 0; q < 4; ++q) {
            int a = __shfl_sync(FULL, offv, q);
            int b = __shfl_sync(FULL, offv, q + 1);
            if (nb + q >= N) { a = 0; b = 0; }
            s_q[q] = a; d_q[q] = b - a;
        }
        int ids[4];
#pragma unroll
        for (int q = 0; q < 4; ++q)
            ids[q] = (lane < d_q[q]) ? g_sorted[s_q[q] + lane] : 0;

        // ---- gather ----
        for (int q = 0; q < 4; ++q) {
            const int nl = wid * 4 + q;
            ull acc2[4] = {0ull, 0ull, 0ull, 0ull};
            const int deg = d_q[q];
            int myE = ids[q];
            for (int p0 = 0; p0 < deg; p0 += 32) {
                if (p0 > 0) myE = (lane < deg - p0) ? g_sorted[s_q[q] + p0 + lane] : 0;
                const int cnt = min(32, deg - p0);
                for (int j0 = 0; j0 < cnt; j0 += 8) {
                    ull m2[8]; longlong2 ww[8];
#pragma unroll
                    for (int t = 0; t < 8; ++t) {
                        int e = __shfl_sync(FULL, myE, (j0 + t) & 31);
                        m2[t] = msg2[(long)e * 32 + lane];
                        ww[t] = gw4[(long)e * 2 + half];
                    }
                    const int jn = min(8, cnt - j0);
#pragma unroll
                    for (int t = 0; t < 8; ++t) {
                        if (t < jn) {
                            float mx, my;
                            unpackf2(m2[t], mx, my);
                            ull mxx = packf2(mx, mx);
                            ull myy = packf2(my, my);
                            acc2[0] = fma2((ull)ww[t].x, mxx, acc2[0]);
                            acc2[1] = fma2((ull)ww[t].x, myy, acc2[1]);
                            acc2[2] = fma2((ull)ww[t].y, mxx, acc2[2]);
                            acc2[3] = fma2((ull)ww[t].y, myy, acc2[3]);
                        }
                    }
                }
            }
            float* arow = A + nl * AH;
#pragma unroll
            for (int kp = 0; kp < 2; ++kp) {
#pragma unroll
                for (int c = 0; c < 2; ++c) {
                    float a, b;
                    unpackf2(acc2[kp * 2 + c], a, b);
                    arow[(2 * kp) * 64 + 2 * lane + c]     = a;
                    arow[(2 * kp + 1) * 64 + 2 * lane + c] = b;
                }
            }
        }
        __syncthreads();

        // ---- GEMM: i-split 2x128; thread tile 2 rows x 8 cols (cA, cB sets) ----
        ull cacc[8];
#pragma unroll
        for (int i2 = 0; i2 < 8; ++i2) cacc[i2] = 0ull;
        const float* a0p = A + (r0 + 0) * AH + ihalf * 128;
        const float* a1p = A + (r0 + 1) * AH + ihalf * 128;
        const float* wbase = Wsm + ihalf * 128 * 64;
#pragma unroll 2
        for (int i = 0; i < 128; i += 4) {
            float4 a0 = *(const float4*)(a0p + i);
            float4 a1 = *(const float4*)(a1p + i);
            float a0v[4] = {a0.x, a0.y, a0.z, a0.w};
            float a1v[4] = {a1.x, a1.y, a1.z, a1.w};
#pragma unroll
            for (int t = 0; t < 4; ++t) {
                const float* wr = wbase + (i + t) * 64;
                longlong2 wA = *(const longlong2*)(wr + cA);
                longlong2 wB = *(const longlong2*)(wr + cB);
                ull av0 = packf2(a0v[t], a0v[t]);
                ull av1 = packf2(a1v[t], a1v[t]);
                cacc[0] = fma2(av0, (ull)wA.x, cacc[0]);
                cacc[1] = fma2(av0, (ull)wA.y, cacc[1]);
                cacc[2] = fma2(av0, (ull)wB.x, cacc[2]);
                cacc[3] = fma2(av0, (ull)wB.y, cacc[3]);
                cacc[4] = fma2(av1, (ull)wA.x, cacc[4]);
                cacc[5] = fma2(av1, (ull)wA.y, cacc[5]);
                cacc[6] = fma2(av1, (ull)wB.x, cacc[6]);
                cacc[7] = fma2(av1, (ull)wB.y, cacc[7]);
            }
        }
        __syncthreads();   // all A reads done before reuse as reduction buffer

        float* red = A;    // 32 rows, stride RSTR=68 (conflict-free)
        if (ihalf == 1) {
#pragma unroll
            for (int r = 0; r < 2; ++r) {
                float y0, y1, y2, y3;
                unpackf2(cacc[r * 4 + 0], y0, y1);
                unpackf2(cacc[r * 4 + 1], y2, y3);
                *(float4*)(red + (r0 + r) * RSTR + cA) = make_float4(y0, y1, y2, y3);
                unpackf2(cacc[r * 4 + 2], y0, y1);
                unpackf2(cacc[r * 4 + 3], y2, y3);
                *(float4*)(red + (r0 + r) * RSTR + cB) = make_float4(y0, y1, y2, y3);
            }
        }
        __syncthreads();
        if (ihalf == 0) {
#pragma unroll
            for (int r = 0; r < 2; ++r) {
                const int nn = n0 + r0 + r;
                if (nn < N) {
                    float4 pA = *(const float4*)(red + (r0 + r) * RSTR + cA);
                    float4 pB = *(const float4*)(red + (r0 + r) * RSTR + cB);
                    float y[8];
                    unpackf2(cacc[r * 4 + 0], y[0], y[1]);
                    unpackf2(cacc[r * 4 + 1], y[2], y[3]);
                    unpackf2(cacc[r * 4 + 2], y[4], y[5]);
                    unpackf2(cacc[r * 4 + 3], y[6], y[7]);
                    *(float4*)(part + (long)nn * 64 + cA) =
                        make_float4(y[0] + pA.x, y[1] + pA.y, y[2] + pA.z, y[3] + pA.w);
                    *(float4*)(part + (long)nn * 64 + cB) =
                        make_float4(y[4] + pB.x, y[5] + pB.y, y[6] + pB.z, y[7] + pB.w);
                }
            }
        }
        __syncthreads();
    }
}

// ============================================================================
// K5: combine halves + bias + leaky relu
// ============================================================================
__global__ __launch_bounds__(256) void k_combine(
    const float* __restrict__ bias, float* __restrict__ out, int n4)
{
    int i = blockIdx.x * 256 + threadIdx.x;
    if (i >= n4) return;
    const float4* p0 = (const float4*)g_part[0];
    const float4* p1 = (const float4*)g_part[1];
    float4 a = p0[i], b = p1[i];
    float4 bb = ((const float4*)bias)[i & 15];
    float y[4] = {a.x + b.x + bb.x, a.y + b.y + bb.y,
                  a.z + b.z + bb.z, a.w + b.w + bb.w};
#pragma unroll
    for (int j = 0; j < 4; ++j) y[j] = (y[j] >= 0.f) ? y[j] : 0.01f * y[j];
    ((float4*)out)[i] = make_float4(y[0], y[1], y[2], y[3]);
}

// ============================================================================
// launch
// ============================================================================
extern "C" void kernel_launch(void* const* d_in, const int* in_sizes, int n_in,
                              void* d_out, int out_size)
{
    const float* msg = (const float*)d_in[0];
    const float* xj  = (const float*)d_in[2];
    const float* eij = (const float*)d_in[3];
    const int*   idx = (const int*)d_in[4];
    const float* kc  = (const float*)d_in[6];
    const float* W   = (const float*)d_in[7];
    const float* b   = (const float*)d_in[8];
    float* out = (float*)d_out;

    const int E = in_sizes[0] / 64;
    const int N = out_size / 64;

    void* degp = nullptr;
    cudaGetSymbolAddress(&degp, g_deg);
    cudaMemsetAsync(degp, 0, (size_t)N * sizeof(int), 0);

    cudaFuncSetAttribute(k_weights, cudaFuncAttributeMaxDynamicSharedMemorySize, K1_SMEM);
    cudaFuncSetAttribute(k_agg_gemm, cudaFuncAttributeMaxDynamicSharedMemorySize, K4_SMEM);

    int eb = (E + 255) / 256;
    k_weights<<<eb, 256, K1_SMEM>>>(xj, eij, idx, kc, E);
    k_scan<<<1, 1024>>>(N);
    k_scatter<<<eb, 256>>>(idx, E);

    int sms = 148;
    cudaDeviceGetAttribute(&sms, cudaDevAttrMultiProcessorCount, 0);
    int nTiles = (N + 31) / 32;
    int nPairs = sms < nTiles ? sms : nTiles;
    k_agg_gemm<<<2 * nPairs, 256, K4_SMEM>>>(msg, W, N, nTiles);

    int n4 = N * 16;
    k_combine<<<(n4 + 255) / 256, 256>>>(b, out, n4);
}